// round 7
// baseline (speedup 1.0000x reference)
#include <cuda_runtime.h>
#include <math.h>

#define NMAX 100000
#define EMAX 1600000
#define DIMF 128

// ---------------- static scratch (no allocations allowed) ----------------
__device__ __align__(16) float g_agg[(size_t)NMAX * DIMF];
__device__ __align__(16) float g_h0 [(size_t)NMAX * DIMF];
__device__ __align__(16) float g_h1 [(size_t)NMAX * DIMF];
__device__ int   g_cnt[NMAX];
__device__ int   g_rowptr[NMAX + 1];
__device__ int   g_cursor[NMAX];
__device__ int   g_csr[EMAX];
__device__ int   g_bsum[128];
__device__ int   g_bsumx[128];
__device__ __align__(16) float g_colsum[DIMF];
__device__ __align__(16) float g_colsq[DIMF];
__device__ __align__(16) float g_scale[DIMF];
__device__ __align__(16) float g_shift[DIMF];

// device-side buffer selection: 0 = external ptr, 1 = g_h0, 2 = g_h1, 3 = g_agg
__device__ __forceinline__ const float* sel_in(int s, const float* ext) {
    if (s == 1) return g_h0;
    if (s == 2) return g_h1;
    if (s == 3) return g_agg;
    return ext;
}
__device__ __forceinline__ float* sel_out(int s, float* ext) {
    if (s == 1) return g_h0;
    if (s == 2) return g_h1;
    if (s == 3) return g_agg;
    return ext;
}

// ---------------- CSR build ----------------
__global__ void k_zero_cnt(int n) {
    int i = blockIdx.x * blockDim.x + threadIdx.x;
    if (i < n) g_cnt[i] = 0;
}

// edge_index is INT32 (JAX default x64-disabled downgrades int64 -> int32)
__global__ void k_hist(const int* __restrict__ dst, int E, int n) {
    int e = blockIdx.x * blockDim.x + threadIdx.x;
    if (e < E) {
        unsigned d = (unsigned)dst[e];
        if (d < (unsigned)n) atomicAdd(&g_cnt[d], 1);
    }
}

// block-wise exclusive scan (1024/block) of g_cnt -> g_rowptr (partial), totals -> g_bsum
__global__ __launch_bounds__(1024) void k_scan1(int n) {
    __shared__ int s[1024];
    int i = blockIdx.x * 1024 + threadIdx.x;
    int v = (i < n) ? g_cnt[i] : 0;
    s[threadIdx.x] = v;
    __syncthreads();
    #pragma unroll
    for (int off = 1; off < 1024; off <<= 1) {
        int t = (threadIdx.x >= off) ? s[threadIdx.x - off] : 0;
        __syncthreads();
        s[threadIdx.x] += t;
        __syncthreads();
    }
    if (i < n) g_rowptr[i] = s[threadIdx.x] - v;  // exclusive
    if (threadIdx.x == 1023) g_bsum[blockIdx.x] = s[1023];
}

// single-block scan of the (<=128) block sums
__global__ void k_scan2(int nb) {
    __shared__ int s[128];
    int v = (threadIdx.x < nb) ? g_bsum[threadIdx.x] : 0;
    s[threadIdx.x] = v;
    __syncthreads();
    #pragma unroll
    for (int off = 1; off < 128; off <<= 1) {
        int t = (threadIdx.x >= off) ? s[threadIdx.x - off] : 0;
        __syncthreads();
        s[threadIdx.x] += t;
        __syncthreads();
    }
    if (threadIdx.x < nb) g_bsumx[threadIdx.x] = s[threadIdx.x] - v;
}

__global__ __launch_bounds__(1024) void k_scan3(int n, int E) {
    int i = blockIdx.x * 1024 + threadIdx.x;
    if (i < n) {
        int v = g_rowptr[i] + g_bsumx[i >> 10];
        g_rowptr[i] = v;
        g_cursor[i] = v;
    }
    if (i == 0) g_rowptr[n] = E;
}

__global__ void k_fill(const int* __restrict__ src,
                       const int* __restrict__ dst, int E, int n) {
    int e = blockIdx.x * blockDim.x + threadIdx.x;
    if (e < E) {
        unsigned d = (unsigned)dst[e];
        unsigned s = (unsigned)src[e];
        if (d < (unsigned)n && s < (unsigned)n) {
            int p = atomicAdd(&g_cursor[d], 1);
            g_csr[p] = (int)s;
        }
    }
}

// ---------------- mean aggregation: 1 warp per node, float4 per lane ----------------
// reads sel_in(selIn, ext), writes g_agg
__global__ void k_aggregate(const float* __restrict__ ext, int selIn, int n) {
    int gw   = (blockIdx.x * blockDim.x + threadIdx.x) >> 5;
    int lane = threadIdx.x & 31;
    if (gw >= n) return;
    const float* in = sel_in(selIn, ext);
    int s0 = g_rowptr[gw], s1 = g_rowptr[gw + 1];
    float4 acc = make_float4(0.f, 0.f, 0.f, 0.f);
    const float4* base = (const float4*)in;
    int lo = lane;  // float4 index within row (32 float4s per row)
    for (int e = s0; e < s1; e++) {
        int s = g_csr[e];
        float4 v = __ldg(&base[(size_t)s * 32 + lo]);
        acc.x += v.x; acc.y += v.y; acc.z += v.z; acc.w += v.w;
    }
    float inv = 1.f / fmaxf((float)(s1 - s0), 1.f);
    acc.x *= inv; acc.y *= inv; acc.z *= inv; acc.w *= inv;
    ((float4*)g_agg)[(size_t)gw * 32 + lo] = acc;
}

// ---------------- fused GEMM: out = agg@Wl + X@Wr + bias  (K=128 each) ----------------
// 128x128 tile, 256 threads, 8x8 microtile, virtual K=256. A = g_agg always.
__global__ __launch_bounds__(256) void k_gemm(
    const float* __restrict__ extX, int selX,
    const float* __restrict__ Wl, const float* __restrict__ Wr,
    const float* __restrict__ bias,
    float* __restrict__ extOut, int selOut,
    int Nrows, int Ncol)
{
    __shared__ float sIn[16][132];  // [k][row] transposed
    __shared__ float sW [16][132];  // [k][col]
    const float* X = sel_in(selX, extX);
    float* out = sel_out(selOut, extOut);

    int tid = threadIdx.x;
    int tileM = blockIdx.x * 128;
    int tm0 = (tid >> 4) * 8;
    int tn0 = (tid & 15) * 8;

    float acc[8][8];
    #pragma unroll
    for (int i = 0; i < 8; i++)
        #pragma unroll
        for (int j = 0; j < 8; j++) acc[i][j] = 0.f;

    int lrow = tid >> 1;         // 0..127
    int lk   = (tid & 1) * 8;    // 0 or 8
    int wkk  = tid >> 4;         // 0..15
    int wcol = (tid & 15) * 8;   // 0..120

    for (int kt = 0; kt < 16; kt++) {
        const float* src = (kt < 8) ? g_agg : X;
        const float* W   = (kt < 8) ? Wl   : Wr;
        int k0 = (kt & 7) * 16;

        // input tile 128x16, store transposed
        int gRow = tileM + lrow;
        float4 v0, v1;
        if (gRow < Nrows) {
            const float4* p = (const float4*)(src + (size_t)gRow * 128 + k0 + lk);
            v0 = p[0]; v1 = p[1];
        } else {
            v0 = make_float4(0.f, 0.f, 0.f, 0.f); v1 = v0;
        }
        sIn[lk + 0][lrow] = v0.x; sIn[lk + 1][lrow] = v0.y;
        sIn[lk + 2][lrow] = v0.z; sIn[lk + 3][lrow] = v0.w;
        sIn[lk + 4][lrow] = v1.x; sIn[lk + 5][lrow] = v1.y;
        sIn[lk + 6][lrow] = v1.z; sIn[lk + 7][lrow] = v1.w;

        // weight tile 16 x Ncol
        if (Ncol == 128) {
            const float4* wp = (const float4*)(W + (size_t)(k0 + wkk) * 128 + wcol);
            float4 w0 = wp[0], w1 = wp[1];
            *(float4*)&sW[wkk][wcol]     = w0;
            *(float4*)&sW[wkk][wcol + 4] = w1;
        } else {
            const float* wp = W + (size_t)(k0 + wkk) * Ncol;
            #pragma unroll
            for (int c = 0; c < 8; c++) {
                int col = wcol + c;
                sW[wkk][col] = (col < Ncol) ? wp[col] : 0.f;
            }
        }
        __syncthreads();

        #pragma unroll
        for (int kk = 0; kk < 16; kk++) {
            float a[8], w[8];
            float4 t;
            t = *(const float4*)&sIn[kk][tm0];     a[0]=t.x; a[1]=t.y; a[2]=t.z; a[3]=t.w;
            t = *(const float4*)&sIn[kk][tm0 + 4]; a[4]=t.x; a[5]=t.y; a[6]=t.z; a[7]=t.w;
            t = *(const float4*)&sW[kk][tn0];      w[0]=t.x; w[1]=t.y; w[2]=t.z; w[3]=t.w;
            t = *(const float4*)&sW[kk][tn0 + 4];  w[4]=t.x; w[5]=t.y; w[6]=t.z; w[7]=t.w;
            #pragma unroll
            for (int i = 0; i < 8; i++)
                #pragma unroll
                for (int j = 0; j < 8; j++)
                    acc[i][j] += a[i] * w[j];
        }
        __syncthreads();
    }

    float b[8];
    #pragma unroll
    for (int j = 0; j < 8; j++)
        b[j] = (tn0 + j < Ncol) ? bias[tn0 + j] : 0.f;

    #pragma unroll
    for (int i = 0; i < 8; i++) {
        int gRow = tileM + tm0 + i;
        if (gRow >= Nrows) continue;
        #pragma unroll
        for (int j = 0; j < 8; j++) {
            int col = tn0 + j;
            if (col < Ncol)
                out[(size_t)gRow * Ncol + col] = acc[i][j] + b[j];
        }
    }
}

// ---------------- BatchNorm ----------------
__global__ void k_zero_cols() {
    if (threadIdx.x < DIMF) { g_colsum[threadIdx.x] = 0.f; g_colsq[threadIdx.x] = 0.f; }
}

__global__ void k_bnreduce(int selH, int Nrows) {
    const float* h = sel_in(selH, (const float*)0);
    __shared__ float ssum[256], ssq[256];
    int col  = threadIdx.x & 127;
    int half = threadIdx.x >> 7;
    float s = 0.f, q = 0.f;
    for (int r = blockIdx.x * 2 + half; r < Nrows; r += gridDim.x * 2) {
        float v = h[(size_t)r * DIMF + col];
        s += v; q += v * v;
    }
    ssum[threadIdx.x] = s; ssq[threadIdx.x] = q;
    __syncthreads();
    if (threadIdx.x < 128) {
        atomicAdd(&g_colsum[col], ssum[threadIdx.x] + ssum[threadIdx.x + 128]);
        atomicAdd(&g_colsq[col],  ssq[threadIdx.x]  + ssq[threadIdx.x + 128]);
    }
}

__global__ void k_bnfinal(const float* __restrict__ gw, const float* __restrict__ be, int Nrows) {
    int i = threadIdx.x;
    if (i < DIMF) {
        float invn = 1.f / (float)Nrows;
        float mu  = g_colsum[i] * invn;
        float var = g_colsq[i] * invn - mu * mu;
        float rs  = rsqrtf(var + 1e-5f);
        float sc  = rs * gw[i];
        g_scale[i] = sc;
        g_shift[i] = be[i] - mu * sc;
    }
}

__global__ void k_bnapply(int selH, int Nrows) {
    float* h = sel_out(selH, (float*)0);
    int idx = blockIdx.x * blockDim.x + threadIdx.x;  // float4 index
    int total = Nrows * 32;
    if (idx >= total) return;
    int col = (idx * 4) & 127;
    float4 v  = ((float4*)h)[idx];
    float4 sc = *(const float4*)&g_scale[col];
    float4 sh = *(const float4*)&g_shift[col];
    v.x = fmaxf(v.x * sc.x + sh.x, 0.f);
    v.y = fmaxf(v.y * sc.y + sh.y, 0.f);
    v.z = fmaxf(v.z * sc.z + sh.z, 0.f);
    v.w = fmaxf(v.w * sc.w + sh.w, 0.f);
    ((float4*)h)[idx] = v;
}

// ---------------- log_softmax over 47 classes, 1 warp per row ----------------
__global__ void k_logsoftmax(float* __restrict__ out, int Nrows, int C) {
    int row  = blockIdx.x * (blockDim.x >> 5) + (threadIdx.x >> 5);
    int lane = threadIdx.x & 31;
    if (row >= Nrows) return;
    float* p = out + (size_t)row * C;
    float v0 = (lane < C)      ? p[lane]      : -1e30f;
    float v1 = (lane + 32 < C) ? p[lane + 32] : -1e30f;
    float m = fmaxf(v0, v1);
    #pragma unroll
    for (int off = 16; off > 0; off >>= 1)
        m = fmaxf(m, __shfl_xor_sync(0xffffffffu, m, off));
    float s = ((lane < C) ? expf(v0 - m) : 0.f) + ((lane + 32 < C) ? expf(v1 - m) : 0.f);
    #pragma unroll
    for (int off = 16; off > 0; off >>= 1)
        s += __shfl_xor_sync(0xffffffffu, s, off);
    float l = m + logf(s);
    if (lane < C)      p[lane]      = v0 - l;
    if (lane + 32 < C) p[lane + 32] = v1 - l;
}

// ---------------- driver (kernel launches ONLY, no runtime API calls) ----------------
static void run_bn(int selH, const float* gw, const float* be, int N) {
    k_zero_cols<<<1, 128>>>();
    k_bnreduce<<<512, 256>>>(selH, N);
    k_bnfinal<<<1, 128>>>(gw, be, N);
    k_bnapply<<<(N * 32 + 255) / 256, 256>>>(selH, N);
}

extern "C" void kernel_launch(void* const* d_in, const int* in_sizes, int n_in,
                              void* d_out, int out_size) {
    const float* x  = (const float*)d_in[0];
    const int*   ei = (const int*)d_in[1];   // int32! (JAX x64-disabled)
    const float* Wl0 = (const float*)d_in[2];
    const float* bl0 = (const float*)d_in[3];
    const float* Wr0 = (const float*)d_in[4];
    const float* g0  = (const float*)d_in[5];
    const float* be0 = (const float*)d_in[6];
    const float* Wl1 = (const float*)d_in[7];
    const float* bl1 = (const float*)d_in[8];
    const float* Wr1 = (const float*)d_in[9];
    const float* g1  = (const float*)d_in[10];
    const float* be1 = (const float*)d_in[11];
    const float* Wl2 = (const float*)d_in[12];
    const float* bl2 = (const float*)d_in[13];
    const float* Wr2 = (const float*)d_in[14];
    float* out = (float*)d_out;

    int N = in_sizes[0] / DIMF;
    int E = in_sizes[1] / 2;
    if (N > NMAX) N = NMAX;
    if (E > EMAX) E = EMAX;
    const int* srcp = ei;       // edge_index[0, :]
    const int* dstp = ei + E;   // edge_index[1, :]
    int C = out_size / N;       // 47

    // --- CSR build ---
    int nb1024 = (N + 1023) / 1024;
    k_zero_cnt<<<(N + 255) / 256, 256>>>(N);
    k_hist<<<(E + 255) / 256, 256>>>(dstp, E, N);
    k_scan1<<<nb1024, 1024>>>(N);
    k_scan2<<<1, 128>>>(nb1024);
    k_scan3<<<nb1024, 1024>>>(N, E);
    k_fill<<<(E + 255) / 256, 256>>>(srcp, dstp, E, N);

    int aggBlocks  = (N + 7) / 8;          // 8 warps/block, 1 warp/node
    int gemmBlocks = (N + 127) / 128;

    // --- layer 0: in = x (ext), h -> g_h0 ---
    k_aggregate<<<aggBlocks, 256>>>(x, 0, N);
    k_gemm<<<gemmBlocks, 256>>>(x, 0, Wl0, Wr0, bl0, (float*)0, 1, N, 128);
    run_bn(1, g0, be0, N);

    // --- layer 1: in = g_h0, h -> g_h1 ---
    k_aggregate<<<aggBlocks, 256>>>((const float*)0, 1, N);
    k_gemm<<<gemmBlocks, 256>>>((const float*)0, 1, Wl1, Wr1, bl1, (float*)0, 2, N, 128);
    run_bn(2, g1, be1, N);

    // --- layer 2: in = g_h1, out = d_out, + log_softmax ---
    k_aggregate<<<aggBlocks, 256>>>((const float*)0, 2, N);
    k_gemm<<<gemmBlocks, 256>>>((const float*)0, 2, Wl2, Wr2, bl2, out, 0, N, C);
    k_logsoftmax<<<(N + 7) / 8, 256>>>(out, N, C);
}

// round 13
// speedup vs baseline: 1.5323x; 1.5323x over previous
#include <cuda_runtime.h>
#include <cuda_bf16.h>
#include <mma.h>
#include <cstdint>
#include <math.h>

using namespace nvcuda;

#define NMAX 100000
#define NPAD 100096      // 782*128
#define EMAX 1600000
#define DIMF 128

// ---------------- static scratch (no allocations allowed) ----------------
__device__ __align__(16) float g_h0 [(size_t)NPAD * DIMF];
__device__ __align__(16) float g_h1 [(size_t)NPAD * DIMF];
// bf16 split tables (hi/lo), padded rows zero-initialized (bss)
__device__ __align__(16) __nv_bfloat16 g_aggH[(size_t)NPAD * DIMF];
__device__ __align__(16) __nv_bfloat16 g_aggL[(size_t)NPAD * DIMF];
__device__ __align__(16) __nv_bfloat16 g_xH  [(size_t)NPAD * DIMF];
__device__ __align__(16) __nv_bfloat16 g_xL  [(size_t)NPAD * DIMF];
__device__ __align__(16) __nv_bfloat16 g_hH  [(size_t)NPAD * DIMF];
__device__ __align__(16) __nv_bfloat16 g_hL  [(size_t)NPAD * DIMF];
// weights transposed+concatenated: [128 rows (out col), 256 cols (k)] bf16
__device__ __align__(16) __nv_bfloat16 g_WtH[128 * 256];
__device__ __align__(16) __nv_bfloat16 g_WtL[128 * 256];

__device__ int   g_cnt[NMAX];
__device__ int   g_rowptr[NMAX + 1];
__device__ int   g_cursor[NMAX];
__device__ int   g_csr[EMAX];
__device__ int   g_bsum[128];
__device__ int   g_bsumx[128];
__device__ __align__(16) float g_colsum[DIMF];
__device__ __align__(16) float g_colsq[DIMF];
__device__ __align__(16) float g_scale[DIMF];
__device__ __align__(16) float g_shift[DIMF];

// sel: 0 = external ptr, 1 = g_h0, 2 = g_h1
__device__ __forceinline__ const float* sel_in(int s, const float* ext) {
    if (s == 1) return g_h0;
    if (s == 2) return g_h1;
    return ext;
}
__device__ __forceinline__ float* sel_out(int s, float* ext) {
    if (s == 1) return g_h0;
    if (s == 2) return g_h1;
    return ext;
}

// split a float into bf16 hi + bf16 lo
__device__ __forceinline__ void split2(float a, __nv_bfloat16& h, __nv_bfloat16& l) {
    h = __float2bfloat16(a);
    l = __float2bfloat16(a - __bfloat162float(h));
}

// ---------------- CSR build ----------------
__global__ void k_zero_cnt(int n) {
    int i = blockIdx.x * blockDim.x + threadIdx.x;
    if (i < n) g_cnt[i] = 0;
}
__global__ void k_hist(const int* __restrict__ dst, int E, int n) {
    int e = blockIdx.x * blockDim.x + threadIdx.x;
    if (e < E) {
        unsigned d = (unsigned)dst[e];
        if (d < (unsigned)n) atomicAdd(&g_cnt[d], 1);
    }
}
__global__ __launch_bounds__(1024) void k_scan1(int n) {
    __shared__ int s[1024];
    int i = blockIdx.x * 1024 + threadIdx.x;
    int v = (i < n) ? g_cnt[i] : 0;
    s[threadIdx.x] = v;
    __syncthreads();
    #pragma unroll
    for (int off = 1; off < 1024; off <<= 1) {
        int t = (threadIdx.x >= off) ? s[threadIdx.x - off] : 0;
        __syncthreads();
        s[threadIdx.x] += t;
        __syncthreads();
    }
    if (i < n) g_rowptr[i] = s[threadIdx.x] - v;
    if (threadIdx.x == 1023) g_bsum[blockIdx.x] = s[1023];
}
__global__ void k_scan2(int nb) {
    __shared__ int s[128];
    int v = (threadIdx.x < nb) ? g_bsum[threadIdx.x] : 0;
    s[threadIdx.x] = v;
    __syncthreads();
    #pragma unroll
    for (int off = 1; off < 128; off <<= 1) {
        int t = (threadIdx.x >= off) ? s[threadIdx.x - off] : 0;
        __syncthreads();
        s[threadIdx.x] += t;
        __syncthreads();
    }
    if (threadIdx.x < nb) g_bsumx[threadIdx.x] = s[threadIdx.x] - v;
}
__global__ __launch_bounds__(1024) void k_scan3(int n, int E) {
    int i = blockIdx.x * 1024 + threadIdx.x;
    if (i < n) {
        int v = g_rowptr[i] + g_bsumx[i >> 10];
        g_rowptr[i] = v;
        g_cursor[i] = v;
    }
    if (i == 0) g_rowptr[n] = E;
}
__global__ void k_fill(const int* __restrict__ src, const int* __restrict__ dst, int E, int n) {
    int e = blockIdx.x * blockDim.x + threadIdx.x;
    if (e < E) {
        unsigned d = (unsigned)dst[e];
        unsigned s = (unsigned)src[e];
        if (d < (unsigned)n && s < (unsigned)n) {
            int p = atomicAdd(&g_cursor[d], 1);
            g_csr[p] = (int)s;
        }
    }
}

// ---------------- mean aggregation -> bf16 split tables ----------------
__global__ void k_aggregate(const float* __restrict__ ext, int selIn, int n) {
    int gw   = (blockIdx.x * blockDim.x + threadIdx.x) >> 5;
    int lane = threadIdx.x & 31;
    if (gw >= n) return;
    const float* in = sel_in(selIn, ext);
    int s0 = g_rowptr[gw], s1 = g_rowptr[gw + 1];
    float4 acc = make_float4(0.f, 0.f, 0.f, 0.f);
    const float4* base = (const float4*)in;
    for (int e = s0; e < s1; e++) {
        int s = g_csr[e];
        float4 v = __ldg(&base[(size_t)s * 32 + lane]);
        acc.x += v.x; acc.y += v.y; acc.z += v.z; acc.w += v.w;
    }
    float inv = 1.f / fmaxf((float)(s1 - s0), 1.f);
    acc.x *= inv; acc.y *= inv; acc.z *= inv; acc.w *= inv;
    union { __nv_bfloat16 h[4]; uint2 u; } ph, pl;
    split2(acc.x, ph.h[0], pl.h[0]);
    split2(acc.y, ph.h[1], pl.h[1]);
    split2(acc.z, ph.h[2], pl.h[2]);
    split2(acc.w, ph.h[3], pl.h[3]);
    size_t o = (size_t)gw * 32 + lane;
    ((uint2*)g_aggH)[o] = ph.u;
    ((uint2*)g_aggL)[o] = pl.u;
}

// ---------------- conversions ----------------
__global__ void k_convX(const float* __restrict__ x, int Nrows) {
    int idx = blockIdx.x * blockDim.x + threadIdx.x;  // float4 index
    if (idx >= Nrows * 32) return;
    float4 v = ((const float4*)x)[idx];
    union { __nv_bfloat16 h[4]; uint2 u; } ph, pl;
    split2(v.x, ph.h[0], pl.h[0]);
    split2(v.y, ph.h[1], pl.h[1]);
    split2(v.z, ph.h[2], pl.h[2]);
    split2(v.w, ph.h[3], pl.h[3]);
    ((uint2*)g_xH)[idx] = ph.u;
    ((uint2*)g_xL)[idx] = pl.u;
}

// weights: Wt[n][k] = k<128 ? Wl[k][n] : Wr[k-128][n], n beyond Ncol -> 0
__global__ void k_convW(const float* __restrict__ Wl, const float* __restrict__ Wr, int Ncol) {
    int idx = blockIdx.x * blockDim.x + threadIdx.x;  // over 128*256
    if (idx >= 128 * 256) return;
    int n = idx >> 8, k = idx & 255;
    float v = 0.f;
    if (n < Ncol) v = (k < 128) ? Wl[k * Ncol + n] : Wr[(k - 128) * Ncol + n];
    __nv_bfloat16 h, l;
    split2(v, h, l);
    g_WtH[idx] = h;
    g_WtL[idx] = l;
}

// ---------------- WMMA bf16x3 GEMM ----------------
// out[128, 64-tile] = [agg | X](128x256) @ Wt(ncol x 256)^T
// 8 warps: 4x2 grid of 32x32 warp tiles. K staged in 8 chunks of 32.
// Layers 0/1 (Ncol==128): bias folded out by BN invariance, direct global store.
// Layer 2 (Ncol==47): bias + log_softmax fused in epilogue via smem.
#define AST 40   // smem row stride (bf16 elems) for A (32 + 8 pad)
#define BST 40

__global__ __launch_bounds__(256) void k_mma(
    int selX, const float* __restrict__ bias,
    float* __restrict__ extOut, int selOut,
    int Nrows, int Ncol)
{
    __shared__ __align__(16) char smemU[131072 / 4];  // 32 KB overlay
    __nv_bfloat16* sAH = (__nv_bfloat16*)smemU;       // 128*40 = 5120 elems
    __nv_bfloat16* sAL = sAH + 128 * AST;
    __nv_bfloat16* sBH = sAL + 128 * AST;             // 64*40 elems
    __nv_bfloat16* sBL = sBH + 64 * BST;
    float* sE = (float*)smemU;                        // 128*64 f32 overlay (epilogue)

    int tid = threadIdx.x;
    int wid = tid >> 5, lid = tid & 31;
    int tileM = blockIdx.x * 128;
    int tileN = blockIdx.y * 64;
    int warpM = wid >> 1;   // 0..3
    int warpN = wid & 1;    // 0..1

    const __nv_bfloat16* XH = selX ? g_hH : g_xH;
    const __nv_bfloat16* XL = selX ? g_hL : g_xL;

    wmma::fragment<wmma::accumulator, 16, 16, 16, float> acc[2][2];
    #pragma unroll
    for (int m = 0; m < 2; m++)
        #pragma unroll
        for (int n = 0; n < 2; n++)
            wmma::fill_fragment(acc[m][n], 0.f);

    for (int chunk = 0; chunk < 8; chunk++) {
        const __nv_bfloat16* tAH = (chunk < 4) ? g_aggH : XH;
        const __nv_bfloat16* tAL = (chunk < 4) ? g_aggL : XL;
        int colA = (chunk & 3) * 32;

        // A: 128 rows x 32 cols, hi+lo (512 uint4 each)
        #pragma unroll
        for (int it = 0; it < 2; it++) {
            int u = it * 256 + tid;
            int r = u >> 2, c8 = (u & 3) * 8;
            size_t g = (size_t)(tileM + r) * 128 + colA + c8;
            *(uint4*)(sAH + r * AST + c8) = *(const uint4*)(tAH + g);
            *(uint4*)(sAL + r * AST + c8) = *(const uint4*)(tAL + g);
        }
        // B: 64 rows x 32 cols, hi+lo (256 uint4 each)
        {
            int r = tid >> 2, c8 = (tid & 3) * 8;
            size_t g = (size_t)(tileN + r) * 256 + chunk * 32 + c8;
            *(uint4*)(sBH + r * BST + c8) = *(const uint4*)(g_WtH + g);
            *(uint4*)(sBL + r * BST + c8) = *(const uint4*)(g_WtL + g);
        }
        __syncthreads();

        #pragma unroll
        for (int ks = 0; ks < 2; ks++) {
            int kb = ks * 16;
            wmma::fragment<wmma::matrix_a, 16, 16, 16, __nv_bfloat16, wmma::row_major> aH[2], aL[2];
            wmma::fragment<wmma::matrix_b, 16, 16, 16, __nv_bfloat16, wmma::col_major> bH[2], bL[2];
            #pragma unroll
            for (int m = 0; m < 2; m++) {
                wmma::load_matrix_sync(aH[m], sAH + (warpM * 32 + m * 16) * AST + kb, AST);
                wmma::load_matrix_sync(aL[m], sAL + (warpM * 32 + m * 16) * AST + kb, AST);
            }
            #pragma unroll
            for (int n = 0; n < 2; n++) {
                wmma::load_matrix_sync(bH[n], sBH + (warpN * 32 + n * 16) * BST + kb, BST);
                wmma::load_matrix_sync(bL[n], sBL + (warpN * 32 + n * 16) * BST + kb, BST);
            }
            #pragma unroll
            for (int m = 0; m < 2; m++)
                #pragma unroll
                for (int n = 0; n < 2; n++) {
                    wmma::mma_sync(acc[m][n], aH[m], bH[n], acc[m][n]);
                    wmma::mma_sync(acc[m][n], aH[m], bL[n], acc[m][n]);
                    wmma::mma_sync(acc[m][n], aL[m], bH[n], acc[m][n]);
                }
        }
        __syncthreads();
    }

    if (Ncol == 128) {
        // bias dropped (BN-invariant); h buffers are NPAD rows -> no row guard
        float* outp = sel_out(selOut, extOut);
        #pragma unroll
        for (int m = 0; m < 2; m++)
            #pragma unroll
            for (int n = 0; n < 2; n++)
                wmma::store_matrix_sync(
                    outp + (size_t)(tileM + warpM * 32 + m * 16) * 128
                         + tileN + warpN * 32 + n * 16,
                    acc[m][n], 128, wmma::mem_row_major);
    } else {
        // layer 2: stash to smem, then fused bias + log_softmax
        #pragma unroll
        for (int m = 0; m < 2; m++)
            #pragma unroll
            for (int n = 0; n < 2; n++)
                wmma::store_matrix_sync(
                    sE + (warpM * 32 + m * 16) * 64 + warpN * 32 + n * 16,
                    acc[m][n], 64, wmma::mem_row_major);
        __syncthreads();

        for (int i = 0; i < 16; i++) {
            int r = wid * 16 + i;
            int row = tileM + r;
            float v0 = (lid < 47)      ? sE[r * 64 + lid]      + bias[lid]      : -1e30f;
            float v1 = (lid + 32 < 47) ? sE[r * 64 + lid + 32] + bias[lid + 32] : -1e30f;
            float mx = fmaxf(v0, v1);
            #pragma unroll
            for (int off = 16; off > 0; off >>= 1)
                mx = fmaxf(mx, __shfl_xor_sync(0xffffffffu, mx, off));
            float s = ((lid < 47) ? expf(v0 - mx) : 0.f) + ((lid + 32 < 47) ? expf(v1 - mx) : 0.f);
            #pragma unroll
            for (int off = 16; off > 0; off >>= 1)
                s += __shfl_xor_sync(0xffffffffu, s, off);
            float l = mx + logf(s);
            if (row < Nrows) {
                if (lid < 47)      extOut[(size_t)row * 47 + lid]      = v0 - l;
                if (lid + 32 < 47) extOut[(size_t)row * 47 + lid + 32] = v1 - l;
            }
        }
    }
}

// ---------------- BatchNorm ----------------
__global__ void k_zero_cols() {
    if (threadIdx.x < DIMF) { g_colsum[threadIdx.x] = 0.f; g_colsq[threadIdx.x] = 0.f; }
}
__global__ void k_bnreduce(int selH, int Nrows) {
    const float* h = sel_in(selH, (const float*)0);
    __shared__ float ssum[256], ssq[256];
    int col  = threadIdx.x & 127;
    int half = threadIdx.x >> 7;
    float s = 0.f, q = 0.f;
    for (int r = blockIdx.x * 2 + half; r < Nrows; r += gridDim.x * 2) {
        float v = h[(size_t)r * DIMF + col];
        s += v; q += v * v;
    }
    ssum[threadIdx.x] = s; ssq[threadIdx.x] = q;
    __syncthreads();
    if (threadIdx.x < 128) {
        atomicAdd(&g_colsum[col], ssum[threadIdx.x] + ssum[threadIdx.x + 128]);
        atomicAdd(&g_colsq[col],  ssq[threadIdx.x]  + ssq[threadIdx.x + 128]);
    }
}
__global__ void k_bnfinal(const float* __restrict__ gw, const float* __restrict__ be, int Nrows) {
    int i = threadIdx.x;
    if (i < DIMF) {
        float invn = 1.f / (float)Nrows;
        float mu  = g_colsum[i] * invn;
        float var = g_colsq[i] * invn - mu * mu;
        float rs  = rsqrtf(var + 1e-5f);
        float sc  = rs * gw[i];
        g_scale[i] = sc;
        g_shift[i] = be[i] - mu * sc;
    }
}
// bn+relu, writes fp32 h (for aggregation) AND bf16 splits (next GEMM X operand)
__global__ void k_bnapply(int selH, int Nrows) {
    float* h = sel_out(selH, (float*)0);
    int idx = blockIdx.x * blockDim.x + threadIdx.x;  // float4 index
    if (idx >= Nrows * 32) return;
    int col = (idx * 4) & 127;
    float4 v  = ((float4*)h)[idx];
    float4 sc = *(const float4*)&g_scale[col];
    float4 sh = *(const float4*)&g_shift[col];
    v.x = fmaxf(v.x * sc.x + sh.x, 0.f);
    v.y = fmaxf(v.y * sc.y + sh.y, 0.f);
    v.z = fmaxf(v.z * sc.z + sh.z, 0.f);
    v.w = fmaxf(v.w * sc.w + sh.w, 0.f);
    ((float4*)h)[idx] = v;
    union { __nv_bfloat16 b[4]; uint2 u; } ph, pl;
    split2(v.x, ph.b[0], pl.b[0]);
    split2(v.y, ph.b[1], pl.b[1]);
    split2(v.z, ph.b[2], pl.b[2]);
    split2(v.w, ph.b[3], pl.b[3]);
    ((uint2*)g_hH)[idx] = ph.u;
    ((uint2*)g_hL)[idx] = pl.u;
}

// ---------------- driver ----------------
static void run_bn(int selH, const float* gw, const float* be, int N) {
    k_zero_cols<<<1, 128>>>();
    k_bnreduce<<<512, 256>>>(selH, N);
    k_bnfinal<<<1, 128>>>(gw, be, N);
    k_bnapply<<<(N * 32 + 255) / 256, 256>>>(selH, N);
}

extern "C" void kernel_launch(void* const* d_in, const int* in_sizes, int n_in,
                              void* d_out, int out_size) {
    const float* x  = (const float*)d_in[0];
    const int*   ei = (const int*)d_in[1];   // int32 (JAX x64-disabled)
    const float* Wl0 = (const float*)d_in[2];
    const float* bl0 = (const float*)d_in[3];
    const float* Wr0 = (const float*)d_in[4];
    const float* g0  = (const float*)d_in[5];
    const float* be0 = (const float*)d_in[6];
    const float* Wl1 = (const float*)d_in[7];
    const float* bl1 = (const float*)d_in[8];
    const float* Wr1 = (const float*)d_in[9];
    const float* g1  = (const float*)d_in[10];
    const float* be1 = (const float*)d_in[11];
    const float* Wl2 = (const float*)d_in[12];
    const float* bl2 = (const float*)d_in[13];
    const float* Wr2 = (const float*)d_in[14];
    float* out = (float*)d_out;

    int N = in_sizes[0] / DIMF;
    int E = in_sizes[1] / 2;
    if (N > NMAX) N = NMAX;
    if (E > EMAX) E = EMAX;
    const int* srcp = ei;
    const int* dstp = ei + E;
    (void)bl0; (void)bl1;  // folded out by BN invariance

    // --- CSR build ---
    int nb1024 = (N + 1023) / 1024;
    k_zero_cnt<<<(N + 255) / 256, 256>>>(N);
    k_hist<<<(E + 255) / 256, 256>>>(dstp, E, N);
    k_scan1<<<nb1024, 1024>>>(N);
    k_scan2<<<1, 128>>>(nb1024);
    k_scan3<<<nb1024, 1024>>>(N, E);
    k_fill<<<(E + 255) / 256, 256>>>(srcp, dstp, E, N);

    int aggBlocks  = (N + 7) / 8;
    int mTiles     = (N + 127) / 128;
    int convBlocks = (N * 32 + 255) / 256;
    dim3 gemmGrid2(mTiles, 2);   // Ncol=128
    dim3 gemmGrid1(mTiles, 1);   // Ncol=47

    k_convX<<<convBlocks, 256>>>(x, N);

    // --- layer 0: agg(x) -> splits; h0 = mma(aggS, xS) ---
    k_convW<<<(128 * 256 + 255) / 256, 256>>>(Wl0, Wr0, 128);
    k_aggregate<<<aggBlocks, 256>>>(x, 0, N);
    k_mma<<<gemmGrid2, 256>>>(0, bl0, (float*)0, 1, N, 128);
    run_bn(1, g0, be0, N);

    // --- layer 1: agg(h0); h1 = mma(aggS, hS) ---
    k_convW<<<(128 * 256 + 255) / 256, 256>>>(Wl1, Wr1, 128);
    k_aggregate<<<aggBlocks, 256>>>((const float*)0, 1, N);
    k_mma<<<gemmGrid2, 256>>>(1, bl1, (float*)0, 2, N, 128);
    run_bn(2, g1, be1, N);

    // --- layer 2: agg(h1); out = log_softmax(mma(aggS, hS) + bias) (fused) ---
    k_convW<<<(128 * 256 + 255) / 256, 256>>>(Wl2, Wr2, 47);
    k_aggregate<<<aggBlocks, 256>>>((const float*)0, 2, N);
    k_mma<<<gemmGrid1, 256>>>(1, bl2, out, 0, N, 47);
}